// round 5
// baseline (speedup 1.0000x reference)
#include <cuda_runtime.h>

// Problem constants (fixed shapes per reference)
#define NUM_EDGES 1000000
#define NUM_USERS 50000
#define NUM_ITEMS 20000
#define NRATE 5
#define NFEAT 64
#define KDIM (NRATE * NFEAT)   // 320

// ---------------------------------------------------------------------------
// Scratch layout (static device array; allocation is forbidden)
// ---------------------------------------------------------------------------
constexpr size_t SUM_U_OFF = 0;
constexpr size_t SUM_V_OFF = (size_t)NUM_USERS * NRATE * NFEAT;              // 16,000,000
constexpr size_t CNT_U_OFF = SUM_V_OFF + (size_t)NUM_ITEMS * NRATE * NFEAT;  // 22,400,000
constexpr size_t CNT_V_OFF = CNT_U_OFF + (size_t)NUM_USERS * NRATE;          // 22,650,000
constexpr size_t SCRATCH_TOTAL = CNT_V_OFF + (size_t)NUM_ITEMS * NRATE;      // 22,750,000 floats (91MB)

__device__ __align__(16) float g_scratch[SCRATCH_TOTAL];

// ---------------------------------------------------------------------------
// PTX helpers
// ---------------------------------------------------------------------------
__device__ __forceinline__ void red_add_v4(float* p, float4 v) {
    unsigned long long gp = (unsigned long long)__cvta_generic_to_global(p);
    asm volatile("red.global.add.v4.f32 [%0], {%1, %2, %3, %4};"
                 :: "l"(gp), "f"(v.x), "f"(v.y), "f"(v.z), "f"(v.w)
                 : "memory");
}
__device__ __forceinline__ unsigned long long pack2(float x, float y) {
    unsigned long long d;
    asm("mov.b64 %0, {%1, %2};" : "=l"(d)
        : "r"(__float_as_uint(x)), "r"(__float_as_uint(y)));
    return d;
}
__device__ __forceinline__ void fma2(unsigned long long& d, unsigned long long a, unsigned long long b) {
    asm("fma.rn.f32x2 %0, %1, %2, %3;" : "=l"(d) : "l"(a), "l"(b), "l"(d));
}
__device__ __forceinline__ void unpack2(unsigned long long d, float& x, float& y) {
    unsigned int lo, hi;
    asm("mov.b64 {%0, %1}, %2;" : "=r"(lo), "=r"(hi) : "l"(d));
    x = __uint_as_float(lo);
    y = __uint_as_float(hi);
}

// ---------------------------------------------------------------------------
// Kernel 1: zero the scratch
// ---------------------------------------------------------------------------
__global__ void __launch_bounds__(256) zero_kernel() {
    size_t i = (size_t)blockIdx.x * blockDim.x + threadIdx.x;
    float4* p = reinterpret_cast<float4*>(g_scratch);
    if (i < SCRATCH_TOTAL / 4) p[i] = make_float4(0.f, 0.f, 0.f, 0.f);
}

// ---------------------------------------------------------------------------
// Kernel 2: edge scatter (unchanged from R4 — control variable this round).
// Half-warp per edge: coalesced 256B feature gather + red.global.add.v4.
// ---------------------------------------------------------------------------
__global__ void __launch_bounds__(256) scatter_kernel(
    const int*   __restrict__ u_s,
    const int*   __restrict__ v_s,
    const int*   __restrict__ rate,
    const float* __restrict__ x_user,
    const float* __restrict__ x_item,
    int E)
{
    int gw   = (blockIdx.x * blockDim.x + threadIdx.x) >> 5;
    int lane = threadIdx.x & 31;
    int hl   = lane & 15;
    int sub  = lane >> 4;
    int base = gw * 8;

    #pragma unroll
    for (int it = 0; it < 4; ++it) {
        int e = base + it * 2 + sub;
        if (e >= E) break;

        int u = __ldg(u_s + e);
        int v = __ldg(v_s + e);
        int r = __ldg(rate + e);

        float4 xi = reinterpret_cast<const float4*>(x_item + (size_t)v * NFEAT)[hl];
        red_add_v4(g_scratch + SUM_U_OFF + ((size_t)u * NRATE + r) * NFEAT + hl * 4, xi);

        float4 xu = reinterpret_cast<const float4*>(x_user + (size_t)u * NFEAT)[hl];
        red_add_v4(g_scratch + SUM_V_OFF + ((size_t)v * NRATE + r) * NFEAT + hl * 4, xu);

        if (hl == 0) {
            atomicAdd(g_scratch + CNT_U_OFF + (size_t)u * NRATE + r, 1.0f);
            atomicAdd(g_scratch + CNT_V_OFF + (size_t)v * NRATE + r, 1.0f);
        }
    }
}

// ---------------------------------------------------------------------------
// Kernel 3: FUSED transform GEMM for both node sets.
//   out[n,h] = sum_k mean[n,k] * W[k,h],  mean[n,k] = sum[n,k]/max(cnt[n,k/64],1)
//
// 1095 blocks (782 user-tiles + 313 item-tiles), 256 threads, 64x64 tile,
// K chunked by 32. Thread (c = t&15, g = t>>4) owns 4 nodes (g*4..) x 4 h
// (c*4..). Inner loop per k: 1 LDS.128 A (4 nodes, warp-broadcast) +
// 1 LDS.128 B (conflict-free phases) + 8 packed fma.rn.f32x2.
// ---------------------------------------------------------------------------
constexpr int UBLOCKS = (NUM_USERS + 63) / 64;   // 782
constexpr int VBLOCKS = (NUM_ITEMS + 63) / 64;   // 313

__global__ void __launch_bounds__(256) transform_fused_kernel(
    const float* __restrict__ W,
    float*       __restrict__ out)
{
    __shared__ float As[32][64];   // [k][node] node-contiguous -> LDS.128 reads
    __shared__ float Bs[32][64];   // [k][h]

    int b = blockIdx.x;
    size_t sum_off, cnt_off;
    int n_nodes, nodeBase;
    float* o;
    if (b < UBLOCKS) {
        sum_off = SUM_U_OFF; cnt_off = CNT_U_OFF;
        n_nodes = NUM_USERS; nodeBase = b * 64; o = out;
    } else {
        sum_off = SUM_V_OFF; cnt_off = CNT_V_OFF;
        n_nodes = NUM_ITEMS; nodeBase = (b - UBLOCKS) * 64;
        o = out + (size_t)NUM_USERS * NFEAT;
    }

    const float* sums = g_scratch + sum_off;
    const float* cnts = g_scratch + cnt_off;

    int t = threadIdx.x;
    int c = t & 15;          // h group: h = 4c..4c+3
    int g = t >> 4;          // node group: nodes g*4..g*4+3 (g in 0..15)

    // A-staging role: node nLoc, 8 consecutive k's starting at ks
    int nLoc = t & 63;
    int ks   = (t >> 6) * 8;

    unsigned long long acc01[4], acc23[4];
    #pragma unroll
    for (int i = 0; i < 4; ++i) { acc01[i] = 0ull; acc23[i] = 0ull; }

    for (int kc = 0; kc < KDIM / 32; ++kc) {
        int k0 = kc * 32;
        int r  = k0 >> 6;    // rating fixed per 32-chunk (chunks align inside 64)

        // ---- stage A: mean = sum * (1/max(cnt,1)) ----
        {
            int n = nodeBase + nLoc;
            bool valid = (n < n_nodes);
            float inv = 0.f;
            if (valid) inv = 1.0f / fmaxf(__ldg(cnts + (size_t)n * NRATE + r), 1.0f);
            const float* src = sums + (size_t)n * KDIM + k0 + ks;
            float4 s0 = valid ? *reinterpret_cast<const float4*>(src)
                              : make_float4(0.f, 0.f, 0.f, 0.f);
            float4 s1 = valid ? *reinterpret_cast<const float4*>(src + 4)
                              : make_float4(0.f, 0.f, 0.f, 0.f);
            As[ks + 0][nLoc] = s0.x * inv;
            As[ks + 1][nLoc] = s0.y * inv;
            As[ks + 2][nLoc] = s0.z * inv;
            As[ks + 3][nLoc] = s0.w * inv;
            As[ks + 4][nLoc] = s1.x * inv;
            As[ks + 5][nLoc] = s1.y * inv;
            As[ks + 6][nLoc] = s1.z * inv;
            As[ks + 7][nLoc] = s1.w * inv;
        }
        // ---- stage B: weight chunk [32][64] coalesced float4 ----
        {
            const float4* wsrc = reinterpret_cast<const float4*>(W + (size_t)k0 * 64);
            float4* bdst = reinterpret_cast<float4*>(&Bs[0][0]);
            bdst[t]       = wsrc[t];
            bdst[t + 256] = wsrc[t + 256];
        }
        __syncthreads();

        // ---- compute: 32 k-steps ----
        #pragma unroll
        for (int k = 0; k < 32; ++k) {
            float4 a4 = *reinterpret_cast<const float4*>(&As[k][g * 4]);
            float4 b4 = *reinterpret_cast<const float4*>(&Bs[k][c * 4]);
            unsigned long long bxy = pack2(b4.x, b4.y);
            unsigned long long bzw = pack2(b4.z, b4.w);
            unsigned long long a0 = pack2(a4.x, a4.x);
            unsigned long long a1 = pack2(a4.y, a4.y);
            unsigned long long a2 = pack2(a4.z, a4.z);
            unsigned long long a3 = pack2(a4.w, a4.w);
            fma2(acc01[0], a0, bxy); fma2(acc23[0], a0, bzw);
            fma2(acc01[1], a1, bxy); fma2(acc23[1], a1, bzw);
            fma2(acc01[2], a2, bxy); fma2(acc23[2], a2, bzw);
            fma2(acc01[3], a3, bxy); fma2(acc23[3], a3, bzw);
        }
        __syncthreads();
    }

    #pragma unroll
    for (int i = 0; i < 4; ++i) {
        int n = nodeBase + g * 4 + i;
        if (n < n_nodes) {
            float4 ov;
            unpack2(acc01[i], ov.x, ov.y);
            unpack2(acc23[i], ov.z, ov.w);
            *reinterpret_cast<float4*>(o + (size_t)n * NFEAT + c * 4) = ov;
        }
    }
}

// ---------------------------------------------------------------------------
// Launch
// ---------------------------------------------------------------------------
extern "C" void kernel_launch(void* const* d_in, const int* in_sizes, int n_in,
                              void* d_out, int out_size)
{
    const int*   u_s    = (const int*)  d_in[0];
    const int*   v_s    = (const int*)  d_in[1];
    const int*   rate   = (const int*)  d_in[2];
    const float* x_user = (const float*)d_in[3];
    const float* x_item = (const float*)d_in[4];
    const float* weight = (const float*)d_in[5];
    float* out = (float*)d_out;

    int E = in_sizes[0];

    int zblocks = (int)((SCRATCH_TOTAL / 4 + 255) / 256);
    zero_kernel<<<zblocks, 256>>>();

    int sblocks = (E + 63) / 64;
    scatter_kernel<<<sblocks, 256>>>(u_s, v_s, rate, x_user, x_item, E);

    transform_fused_kernel<<<UBLOCKS + VBLOCKS, 256>>>(weight, out);
}